// round 12
// baseline (speedup 1.0000x reference)
#include <cuda_runtime.h>
#include <cuda_fp16.h>
#include <math.h>
#include <stdint.h>

// ---------------- problem constants ----------------
#define B_  8
#define S_  8192
#define D_  512
#define H_  256
#define M_  (B_*S_)            // 65536 rows
#define N3H (3*H_)             // 768

// ---------------- GEMM tiling (mma.sync path) ----------------
#define MT   128               // m rows per CTA (= one scan chunk)
#define CH   64                // channels per CTA
#define NT   192               // W rows per CTA = 3 gates x 64 ch
#define NTILES 4               // 256 / 64
#define KS   64                // k per SMEM stage (64 fp16 = 128 B rows, SW128)
#define NKS  (D_/KS)           // 8
#define A_BYTES (MT*128)       // 16384  (x fp16)
#define B_BYTES (NT*128)       // 24576  (W fp16)
#define STAGE_BYTES (A_BYTES + B_BYTES)       // 40960
#define SMEM_DYN (2*STAGE_BYTES)              // 81920

// scan chunking
#define LCH 128
#define NCH (S_/LCH)           // 64

// ---------------- device scratch ----------------
__device__ __half g_wh[(size_t)N3H*D_];          // permuted [nt][192][512]
__device__ __half g_a[(size_t)M_*H_];            // forget gate (fp16)
__device__ __half g_c[(size_t)M_*H_];            // input contribution (fp16)
__device__ float g_Ae[(size_t)B_*NCH*H_];
__device__ float g_Be[(size_t)B_*NCH*H_];
__device__ float g_h0[(size_t)B_*NCH*H_];

// ---------------- PTX helpers ----------------
__device__ __forceinline__ uint32_t smem_u32(const void* p) {
    uint32_t a;
    asm("{ .reg .u64 t; cvta.to.shared.u64 t, %1; cvt.u32.u64 %0, t; }" : "=r"(a) : "l"(p));
    return a;
}
#define CP16(dst, src) asm volatile("cp.async.cg.shared.global [%0], [%1], 16;" :: "r"(dst), "l"(src) : "memory")
#define CP_COMMIT()    asm volatile("cp.async.commit_group;" ::: "memory")
#define CP_WAIT1()     asm volatile("cp.async.wait_group 1;" ::: "memory")
#define CP_WAIT0()     asm volatile("cp.async.wait_group 0;" ::: "memory")
#define SWZ(o) ((o) ^ (((o) >> 3) & 0x70))

__device__ __forceinline__ void ldsm4(uint32_t* r, uint32_t addr) {
    asm volatile("ldmatrix.sync.aligned.m8n8.x4.shared.b16 {%0,%1,%2,%3}, [%4];"
                 : "=r"(r[0]), "=r"(r[1]), "=r"(r[2]), "=r"(r[3]) : "r"(addr));
}
__device__ __forceinline__ void mma16816(float* d, const uint32_t* a,
                                         uint32_t b0, uint32_t b1) {
    asm volatile("mma.sync.aligned.m16n8k16.row.col.f32.f16.f16.f32 "
                 "{%0,%1,%2,%3}, {%4,%5,%6,%7}, {%8,%9}, {%0,%1,%2,%3};"
                 : "+f"(d[0]), "+f"(d[1]), "+f"(d[2]), "+f"(d[3])
                 : "r"(a[0]), "r"(a[1]), "r"(a[2]), "r"(a[3]), "r"(b0), "r"(b1));
}

// ---------------------------------------------------------------------------
// W conversion/permute (tiny: 1.5 MB)
// ---------------------------------------------------------------------------
__global__ __launch_bounds__(256) void k_conv_w(const float* __restrict__ W)
{
    size_t i = ((size_t)blockIdx.x * blockDim.x + threadIdx.x) * 4;
    int r = (int)(i / D_);                 // src row 0..767
    int k = (int)(i % D_);
    int gate = r / H_, ch = r % H_;
    int ntv = ch / CH;
    size_t dst = ((size_t)(ntv * NT + gate * CH + (ch % CH))) * D_ + k;
    float4 v = *(const float4*)&W[i];
    g_wh[dst]   = __float2half(v.x);
    g_wh[dst+1] = __float2half(v.y);
    g_wh[dst+2] = __float2half(v.z);
    g_wh[dst+3] = __float2half(v.w);
}

// ---------------------------------------------------------------------------
// mma.sync fp16 GEMM + fused gate epilogue + fused per-chunk scan reduction.
// Gate algebra (exact): e^{softplus(z)} = 1+e^z, so with ef=e^{-f}, ei=e^{-i}:
//   f' = (1+ei)/(2+ef+ei),  i' = (1+ef)/(2+ef+ei)   -- one shared reciprocal.
// grid = (NTILES, M_/MT) = (4, 512); 256 threads (8 warps).
// ---------------------------------------------------------------------------
__global__ __launch_bounds__(256, 1) void k_gemm_mma(const float* __restrict__ x)
{
    extern __shared__ char dynsmem[];
    const uint32_t sb = smem_u32(dynsmem);

    const int tid  = threadIdx.x;
    const int warp = tid >> 5;
    const int lane = tid & 31;
    const int warp_m = warp & 3;           // 0..3
    const int warp_c = warp >> 2;          // 0..1
    const int nt = blockIdx.x;
    const int m0 = blockIdx.y * MT;
    const int r0 = nt * NT;                // row base in permuted W

    float acc[3][2][4][4];
#pragma unroll
    for (int g = 0; g < 3; g++)
#pragma unroll
        for (int mf = 0; mf < 2; mf++)
#pragma unroll
            for (int nf = 0; nf < 4; nf++)
#pragma unroll
                for (int e = 0; e < 4; e++) acc[g][mf][nf][e] = 0.0f;

    // A tile: 128 rows x 64 k fp32 -> fp16. Per thread: 4 chunks of 8 floats.
    float4 av[8];
    auto lda = [&](int ks) {
        const int kb = ks * KS;
#pragma unroll
        for (int it = 0; it < 4; it++) {
            int id = it * 256 + tid, row = id >> 3, cq = id & 7;
            size_t so = (size_t)(m0 + row) * D_ + kb + cq * 8;
            av[2 * it]     = *(const float4*)&x[so];
            av[2 * it + 1] = *(const float4*)&x[so + 4];
        }
    };
    auto sta = [&](int ks) {
        const int st = ks & 1;
#pragma unroll
        for (int it = 0; it < 4; it++) {
            int id = it * 256 + tid, row = id >> 3, cq = id & 7;
            uint32_t d = SWZ((uint32_t)(row * 128 + cq * 16));
            __half2 h0 = __floats2half2_rn(av[2 * it].x,     av[2 * it].y);
            __half2 h1 = __floats2half2_rn(av[2 * it].z,     av[2 * it].w);
            __half2 h2 = __floats2half2_rn(av[2 * it + 1].x, av[2 * it + 1].y);
            __half2 h3 = __floats2half2_rn(av[2 * it + 1].z, av[2 * it + 1].w);
            uint4 u;
            u.x = *(uint32_t*)&h0; u.y = *(uint32_t*)&h1;
            u.z = *(uint32_t*)&h2; u.w = *(uint32_t*)&h3;
            *(uint4*)(dynsmem + st * STAGE_BYTES + d) = u;
        }
    };
    auto prefetch_w = [&](int ks) {
        const int st = ks & 1;
        const uint32_t bh = sb + st * STAGE_BYTES + A_BYTES;
        const int kb = ks * KS;
#pragma unroll
        for (int it = 0; it < 6; it++) {   // B: 192 rows x 8 chunks = 1536
            int id = it * 256 + tid, row = id >> 3, cq = id & 7;
            uint32_t d = SWZ((uint32_t)(row * 128 + cq * 16));
            size_t so = (size_t)(r0 + row) * D_ + kb + cq * 8;
            CP16(bh + d, (const void*)(g_wh + so));
        }
        CP_COMMIT();
    };

    lda(0); sta(0);
    prefetch_w(0);

    const int arow = warp_m * 32 + (lane & 15);     // + mf*16
    const int ahalf = (lane >> 4) * 16;             // 16B k-half select
    const int brow = warp_c * 32 + (lane & 15);     // + gate*64 (+16 second half)

    for (int ks = 0; ks < NKS; ks++) {
        if (ks + 1 < NKS) { lda(ks + 1); prefetch_w(ks + 1); CP_WAIT1(); }
        else             { CP_WAIT0(); }
        __syncthreads();

        const int st = ks & 1;
        const uint32_t ab_b = sb + st * STAGE_BYTES;
        const uint32_t bh_b = ab_b + A_BYTES;

#pragma unroll
        for (int k16 = 0; k16 < 4; k16++) {
            const uint32_t kbyte = (uint32_t)(k16 * 32 + ahalf);
            uint32_t ahf[2][4];
#pragma unroll
            for (int mf = 0; mf < 2; mf++) {
                uint32_t off = SWZ((uint32_t)((arow + mf * 16) * 128) + kbyte);
                ldsm4(ahf[mf], ab_b + off);
            }
#pragma unroll
            for (int g = 0; g < 3; g++) {
                uint32_t bhf[2][4];
#pragma unroll
                for (int half = 0; half < 2; half++) {
                    uint32_t off = SWZ((uint32_t)((g * 64 + brow + half * 16) * 128) + kbyte);
                    ldsm4(bhf[half], bh_b + off);
                }
#pragma unroll
                for (int mf = 0; mf < 2; mf++) {
#pragma unroll
                    for (int nf = 0; nf < 4; nf++) {
                        const int hv = nf >> 1, pr = nf & 1;
                        mma16816(acc[g][mf][nf], ahf[mf], bhf[hv][pr], bhf[hv][pr + 2]);
                    }
                }
            }
        }
        if (ks + 1 < NKS) sta(ks + 1);      // next iter's __syncthreads publishes
    }
    __syncthreads();                         // smem reuse for sA/sC below

    // ---- fused gate epilogue: write a,c to gmem (fp16) + stage into smem ----
    float* sA = (float*)dynsmem;                 // [128][65] padded
    float* sC = sA + 128 * 65;

    const int chl_base = warp_c * 32 + (lane & 3) * 2;
    const int ch_gbase = nt * CH + chl_base;
    const int m_base   = m0 + warp_m * 32 + (lane >> 2);
#pragma unroll
    for (int mf = 0; mf < 2; mf++) {
#pragma unroll
        for (int nf = 0; nf < 4; nf++) {
#pragma unroll
            for (int r2 = 0; r2 < 2; r2++) {
                const int m = m_base + mf * 16 + r2 * 8;
                const int t = m - m0;
                float fpv[2], cv[2];
#pragma unroll
                for (int e = 0; e < 2; e++) {
                    float f  = acc[0][mf][nf][2 * r2 + e];
                    float iv = acc[1][mf][nf][2 * r2 + e];
                    float hv = acc[2][mf][nf][2 * r2 + e];
                    float ef = __expf(-f);
                    float ei = __expf(-iv);
                    float r  = __fdividef(1.0f, 2.0f + ef + ei);
                    float fp = (1.0f + ei) * r;          // sigmoid(-diff)
                    float ip = (1.0f + ef) * r;          // sigmoid(diff)
                    float gv = (hv >= 0.0f) ? (hv + 0.5f)
                             : __fdividef(1.0f, 1.0f + __expf(-hv));
                    fpv[e] = fp;
                    cv[e]  = ip * gv;
                    const int chl = chl_base + nf * 8 + e;
                    sA[t * 65 + chl] = fp;
                    sC[t * 65 + chl] = cv[e];
                }
                size_t o = (size_t)m * H_ + ch_gbase + nf * 8;
                *(__half2*)&g_a[o] = __floats2half2_rn(fpv[0], fpv[1]);
                *(__half2*)&g_c[o] = __floats2half2_rn(cv[0],  cv[1]);
            }
        }
    }
    __syncthreads();

    // ---- fused chunk reduction: 64 threads, one per channel ----
    if (tid < 64) {
        float A = 1.0f, Bv = 0.0f;
#pragma unroll 8
        for (int t = 0; t < LCH; t++) {
            const float a = sA[t * 65 + tid];
            const float c = sC[t * 65 + tid];
            Bv = fmaf(a, Bv, c);
            A *= a;
        }
        const int b   = m0 >> 13;
        const int chk = (m0 & 8191) >> 7;
        const size_t o = (size_t)(b * NCH + chk) * H_ + nt * CH + tid;
        g_Ae[o] = A;
        g_Be[o] = Bv;
    }
}

// ---------------------------------------------------------------------------
// cross-chunk chain: one warp per (b,h) channel; lane owns chunks 2l, 2l+1.
// ---------------------------------------------------------------------------
__global__ __launch_bounds__(256) void k_chain(const float* __restrict__ h_prev)
{
    const int gw   = (blockIdx.x * blockDim.x + threadIdx.x) >> 5;  // channel id
    const int lane = threadIdx.x & 31;
    const int b = gw / H_;
    const int h = gw % H_;

    const size_t o0 = ((size_t)(b * NCH + 2 * lane)) * H_ + h;
    const float A0 = g_Ae[o0],       B0 = g_Be[o0];
    const float A1 = g_Ae[o0 + H_],  B1 = g_Be[o0 + H_];

    float As = A0 * A1;
    float Bs = fmaf(A1, B0, B1);

#pragma unroll
    for (int d = 1; d < 32; d <<= 1) {
        float Au = __shfl_up_sync(0xFFFFFFFFu, As, d);
        float Bu = __shfl_up_sync(0xFFFFFFFFu, Bs, d);
        if (lane >= d) {
            Bs = fmaf(As, Bu, Bs);
            As = As * Au;
        }
    }
    float Ae = __shfl_up_sync(0xFFFFFFFFu, As, 1);
    float Be = __shfl_up_sync(0xFFFFFFFFu, Bs, 1);
    if (lane == 0) { Ae = 1.0f; Be = 0.0f; }

    const float z = h_prev[b * H_ + h];
    const float init = (z >= 0.0f) ? (z + 0.5f) : 1.0f / (1.0f + __expf(-z));

    const float h0a = fmaf(Ae, init, Be);
    const float h0b = fmaf(A0, h0a, B0);
    g_h0[o0]      = h0a;
    g_h0[o0 + H_] = h0b;
}

// ---------------------------------------------------------------------------
// output replay: 256 threads per (b,chunk), one channel per thread.
// ---------------------------------------------------------------------------
__global__ __launch_bounds__(256) void k_out(float* __restrict__ out)
{
    const int bc = blockIdx.x;
    const int b  = bc / NCH;
    const int ch = bc % NCH;
    const int h  = threadIdx.x;
    size_t base = ((size_t)b * S_ + (size_t)ch * LCH) * H_ + h;

    float hc = g_h0[(size_t)bc * H_ + h];
#pragma unroll 8
    for (int t = 0; t < LCH; t++) {
        const size_t o = base + (size_t)t * H_;
        const float a = __half2float(g_a[o]);
        const float c = __half2float(g_c[o]);
        hc = fmaf(a, hc, c);
        out[o] = hc;
    }
}

// ---------------------------------------------------------------------------
extern "C" void kernel_launch(void* const* d_in, const int* in_sizes, int n_in,
                              void* d_out, int out_size)
{
    const float* x  = nullptr;
    const float* hp = nullptr;
    const float* Wp = nullptr;
    for (int i = 0; i < n_in; i++) {
        if      (in_sizes[i] == M_ * D_)      x  = (const float*)d_in[i];
        else if (in_sizes[i] == B_ * H_)      hp = (const float*)d_in[i];
        else if (in_sizes[i] == 3 * H_ * D_)  Wp = (const float*)d_in[i];
    }
    float* out = (float*)d_out;

    cudaFuncSetAttribute(k_gemm_mma, cudaFuncAttributeMaxDynamicSharedMemorySize, SMEM_DYN);

    k_conv_w<<<(N3H * D_) / (256 * 4), 256>>>(Wp);

    dim3 gg(NTILES, M_ / MT);          // (4, 512)
    k_gemm_mma<<<gg, 256, SMEM_DYN>>>(x);

    k_chain<<<(B_ * H_ * 32) / 256, 256>>>(hp);
    k_out<<<B_ * NCH, 256>>>(out);
}

// round 15
// speedup vs baseline: 1.4512x; 1.4512x over previous
#include <cuda_runtime.h>
#include <cuda_fp16.h>
#include <math.h>
#include <stdint.h>

// ---------------- problem constants ----------------
#define B_  8
#define S_  8192
#define D_  512
#define H_  256
#define M_  (B_*S_)            // 65536 rows
#define N3H (3*H_)             // 768

// ---------------- GEMM tiling (mma.sync path) ----------------
#define MT   128               // m rows per CTA (= one scan chunk)
#define CH   64                // channels per CTA
#define NT   192               // W rows per CTA = 3 gates x 64 ch
#define NTILES 4               // 256 / 64
#define KS   64                // k per SMEM stage (64 fp16 = 128 B rows, SW128)
#define NKS  (D_/KS)           // 8
#define A_BYTES (MT*128)       // 16384  (x fp16)
#define B_BYTES (NT*128)       // 24576  (W fp16)
#define STAGE_BYTES (A_BYTES + B_BYTES)       // 40960
#define SMEM_DYN (2*STAGE_BYTES)              // 81920

// scan chunking
#define LCH 128
#define NCH (S_/LCH)           // 64

// ---------------- device scratch ----------------
__device__ __half g_wh[(size_t)N3H*D_];          // permuted [nt][192][512]
__device__ __half g_a[(size_t)M_*H_];            // forget gate (fp16)
__device__ __half g_c[(size_t)M_*H_];            // input contribution (fp16)
__device__ float g_Ae[(size_t)B_*NCH*H_];
__device__ float g_Be[(size_t)B_*NCH*H_];
__device__ float g_h0[(size_t)B_*NCH*H_];

// ---------------- PTX helpers ----------------
__device__ __forceinline__ uint32_t smem_u32(const void* p) {
    uint32_t a;
    asm("{ .reg .u64 t; cvta.to.shared.u64 t, %1; cvt.u32.u64 %0, t; }" : "=r"(a) : "l"(p));
    return a;
}
#define CP16(dst, src) asm volatile("cp.async.cg.shared.global [%0], [%1], 16;" :: "r"(dst), "l"(src) : "memory")
#define CP_COMMIT()    asm volatile("cp.async.commit_group;" ::: "memory")
#define CP_WAIT1()     asm volatile("cp.async.wait_group 1;" ::: "memory")
#define CP_WAIT0()     asm volatile("cp.async.wait_group 0;" ::: "memory")
#define SWZ(o) ((o) ^ (((o) >> 3) & 0x70))

__device__ __forceinline__ void ldsm4(uint32_t* r, uint32_t addr) {
    asm volatile("ldmatrix.sync.aligned.m8n8.x4.shared.b16 {%0,%1,%2,%3}, [%4];"
                 : "=r"(r[0]), "=r"(r[1]), "=r"(r[2]), "=r"(r[3]) : "r"(addr));
}
__device__ __forceinline__ void mma16816(float* d, const uint32_t* a,
                                         uint32_t b0, uint32_t b1) {
    asm volatile("mma.sync.aligned.m16n8k16.row.col.f32.f16.f16.f32 "
                 "{%0,%1,%2,%3}, {%4,%5,%6,%7}, {%8,%9}, {%0,%1,%2,%3};"
                 : "+f"(d[0]), "+f"(d[1]), "+f"(d[2]), "+f"(d[3])
                 : "r"(a[0]), "r"(a[1]), "r"(a[2]), "r"(a[3]), "r"(b0), "r"(b1));
}

// ---------------------------------------------------------------------------
// W conversion/permute (tiny: 1.5 MB)
// ---------------------------------------------------------------------------
__global__ __launch_bounds__(256) void k_conv_w(const float* __restrict__ W)
{
    size_t i = ((size_t)blockIdx.x * blockDim.x + threadIdx.x) * 4;
    int r = (int)(i / D_);                 // src row 0..767
    int k = (int)(i % D_);
    int gate = r / H_, ch = r % H_;
    int ntv = ch / CH;
    size_t dst = ((size_t)(ntv * NT + gate * CH + (ch % CH))) * D_ + k;
    float4 v = *(const float4*)&W[i];
    g_wh[dst]   = __float2half(v.x);
    g_wh[dst+1] = __float2half(v.y);
    g_wh[dst+2] = __float2half(v.z);
    g_wh[dst+3] = __float2half(v.w);
}

// ---------------------------------------------------------------------------
// mma.sync fp16 GEMM + fused gate epilogue + fused per-chunk scan reduction.
// Gate algebra (exact): e^{softplus(z)} = 1+e^z, so with ef=e^{-f}, ei=e^{-i}:
//   f' = (1+ei)/(2+ef+ei),  i' = (1+ef)/(2+ef+ei)   -- one shared reciprocal.
// grid = (NTILES, M_/MT) = (4, 512); 256 threads (8 warps).
// ---------------------------------------------------------------------------
__global__ __launch_bounds__(256, 1) void k_gemm_mma(const float* __restrict__ x)
{
    extern __shared__ char dynsmem[];
    const uint32_t sb = smem_u32(dynsmem);

    const int tid  = threadIdx.x;
    const int warp = tid >> 5;
    const int lane = tid & 31;
    const int warp_m = warp & 3;           // 0..3
    const int warp_c = warp >> 2;          // 0..1
    const int nt = blockIdx.x;
    const int m0 = blockIdx.y * MT;
    const int r0 = nt * NT;                // row base in permuted W

    float acc[3][2][4][4];
#pragma unroll
    for (int g = 0; g < 3; g++)
#pragma unroll
        for (int mf = 0; mf < 2; mf++)
#pragma unroll
            for (int nf = 0; nf < 4; nf++)
#pragma unroll
                for (int e = 0; e < 4; e++) acc[g][mf][nf][e] = 0.0f;

    // A tile: 128 rows x 64 k fp32 -> fp16. Per thread: 4 chunks of 8 floats.
    float4 av[8];
    auto lda = [&](int ks) {
        const int kb = ks * KS;
#pragma unroll
        for (int it = 0; it < 4; it++) {
            int id = it * 256 + tid, row = id >> 3, cq = id & 7;
            size_t so = (size_t)(m0 + row) * D_ + kb + cq * 8;
            av[2 * it]     = *(const float4*)&x[so];
            av[2 * it + 1] = *(const float4*)&x[so + 4];
        }
    };
    auto sta = [&](int ks) {
        const int st = ks & 1;
#pragma unroll
        for (int it = 0; it < 4; it++) {
            int id = it * 256 + tid, row = id >> 3, cq = id & 7;
            uint32_t d = SWZ((uint32_t)(row * 128 + cq * 16));
            __half2 h0 = __floats2half2_rn(av[2 * it].x,     av[2 * it].y);
            __half2 h1 = __floats2half2_rn(av[2 * it].z,     av[2 * it].w);
            __half2 h2 = __floats2half2_rn(av[2 * it + 1].x, av[2 * it + 1].y);
            __half2 h3 = __floats2half2_rn(av[2 * it + 1].z, av[2 * it + 1].w);
            uint4 u;
            u.x = *(uint32_t*)&h0; u.y = *(uint32_t*)&h1;
            u.z = *(uint32_t*)&h2; u.w = *(uint32_t*)&h3;
            *(uint4*)(dynsmem + st * STAGE_BYTES + d) = u;
        }
    };
    auto prefetch_w = [&](int ks) {
        const int st = ks & 1;
        const uint32_t bh = sb + st * STAGE_BYTES + A_BYTES;
        const int kb = ks * KS;
#pragma unroll
        for (int it = 0; it < 6; it++) {   // B: 192 rows x 8 chunks = 1536
            int id = it * 256 + tid, row = id >> 3, cq = id & 7;
            uint32_t d = SWZ((uint32_t)(row * 128 + cq * 16));
            size_t so = (size_t)(r0 + row) * D_ + kb + cq * 8;
            CP16(bh + d, (const void*)(g_wh + so));
        }
        CP_COMMIT();
    };

    lda(0); sta(0);
    prefetch_w(0);

    const int arow = warp_m * 32 + (lane & 15);     // + mf*16
    const int ahalf = (lane >> 4) * 16;             // 16B k-half select
    const int brow = warp_c * 32 + (lane & 15);     // + gate*64 (+16 second half)

    for (int ks = 0; ks < NKS; ks++) {
        if (ks + 1 < NKS) { lda(ks + 1); prefetch_w(ks + 1); CP_WAIT1(); }
        else             { CP_WAIT0(); }
        __syncthreads();

        const int st = ks & 1;
        const uint32_t ab_b = sb + st * STAGE_BYTES;
        const uint32_t bh_b = ab_b + A_BYTES;

#pragma unroll
        for (int k16 = 0; k16 < 4; k16++) {
            const uint32_t kbyte = (uint32_t)(k16 * 32 + ahalf);
            uint32_t ahf[2][4];
#pragma unroll
            for (int mf = 0; mf < 2; mf++) {
                uint32_t off = SWZ((uint32_t)((arow + mf * 16) * 128) + kbyte);
                ldsm4(ahf[mf], ab_b + off);
            }
#pragma unroll
            for (int g = 0; g < 3; g++) {
                uint32_t bhf[2][4];
#pragma unroll
                for (int half = 0; half < 2; half++) {
                    uint32_t off = SWZ((uint32_t)((g * 64 + brow + half * 16) * 128) + kbyte);
                    ldsm4(bhf[half], bh_b + off);
                }
#pragma unroll
                for (int mf = 0; mf < 2; mf++) {
#pragma unroll
                    for (int nf = 0; nf < 4; nf++) {
                        const int hv = nf >> 1, pr = nf & 1;
                        mma16816(acc[g][mf][nf], ahf[mf], bhf[hv][pr], bhf[hv][pr + 2]);
                    }
                }
            }
        }
        if (ks + 1 < NKS) sta(ks + 1);      // next iter's __syncthreads publishes
    }
    __syncthreads();                         // smem reuse for sA/sC below

    // ---- fused gate epilogue: write a,c to gmem (fp16) + stage into smem ----
    float* sA = (float*)dynsmem;                 // [128][65] padded
    float* sC = sA + 128 * 65;

    const int chl_base = warp_c * 32 + (lane & 3) * 2;
    const int ch_gbase = nt * CH + chl_base;
    const int m_base   = m0 + warp_m * 32 + (lane >> 2);
#pragma unroll
    for (int mf = 0; mf < 2; mf++) {
#pragma unroll
        for (int nf = 0; nf < 4; nf++) {
#pragma unroll
            for (int r2 = 0; r2 < 2; r2++) {
                const int m = m_base + mf * 16 + r2 * 8;
                const int t = m - m0;
                float fpv[2], cv[2];
#pragma unroll
                for (int e = 0; e < 2; e++) {
                    float f  = acc[0][mf][nf][2 * r2 + e];
                    float iv = acc[1][mf][nf][2 * r2 + e];
                    float hv = acc[2][mf][nf][2 * r2 + e];
                    float ef = __expf(-f);
                    float ei = __expf(-iv);
                    float r  = __fdividef(1.0f, 2.0f + ef + ei);
                    float fp = (1.0f + ei) * r;          // sigmoid(-diff)
                    float ip = (1.0f + ef) * r;          // sigmoid(diff)
                    float gv = (hv >= 0.0f) ? (hv + 0.5f)
                             : __fdividef(1.0f, 1.0f + __expf(-hv));
                    fpv[e] = fp;
                    cv[e]  = ip * gv;
                    const int chl = chl_base + nf * 8 + e;
                    sA[t * 65 + chl] = fp;
                    sC[t * 65 + chl] = cv[e];
                }
                size_t o = (size_t)m * H_ + ch_gbase + nf * 8;
                *(__half2*)&g_a[o] = __floats2half2_rn(fpv[0], fpv[1]);
                *(__half2*)&g_c[o] = __floats2half2_rn(cv[0],  cv[1]);
            }
        }
    }
    __syncthreads();

    // ---- fused chunk reduction: 64 threads, one per channel ----
    if (tid < 64) {
        float A = 1.0f, Bv = 0.0f;
#pragma unroll 8
        for (int t = 0; t < LCH; t++) {
            const float a = sA[t * 65 + tid];
            const float c = sC[t * 65 + tid];
            Bv = fmaf(a, Bv, c);
            A *= a;
        }
        const int b   = m0 >> 13;
        const int chk = (m0 & 8191) >> 7;
        const size_t o = (size_t)(b * NCH + chk) * H_ + nt * CH + tid;
        g_Ae[o] = A;
        g_Be[o] = Bv;
    }
}

// ---------------------------------------------------------------------------
// cross-chunk chain: one warp per (b,h) channel; lane owns chunks 2l, 2l+1.
// ---------------------------------------------------------------------------
__global__ __launch_bounds__(256) void k_chain(const float* __restrict__ h_prev)
{
    const int gw   = (blockIdx.x * blockDim.x + threadIdx.x) >> 5;  // channel id
    const int lane = threadIdx.x & 31;
    const int b = gw / H_;
    const int h = gw % H_;

    const size_t o0 = ((size_t)(b * NCH + 2 * lane)) * H_ + h;
    const float A0 = g_Ae[o0],       B0 = g_Be[o0];
    const float A1 = g_Ae[o0 + H_],  B1 = g_Be[o0 + H_];

    float As = A0 * A1;
    float Bs = fmaf(A1, B0, B1);

#pragma unroll
    for (int d = 1; d < 32; d <<= 1) {
        float Au = __shfl_up_sync(0xFFFFFFFFu, As, d);
        float Bu = __shfl_up_sync(0xFFFFFFFFu, Bs, d);
        if (lane >= d) {
            Bs = fmaf(As, Bu, Bs);
            As = As * Au;
        }
    }
    float Ae = __shfl_up_sync(0xFFFFFFFFu, As, 1);
    float Be = __shfl_up_sync(0xFFFFFFFFu, Bs, 1);
    if (lane == 0) { Ae = 1.0f; Be = 0.0f; }

    const float z = h_prev[b * H_ + h];
    const float init = (z >= 0.0f) ? (z + 0.5f) : 1.0f / (1.0f + __expf(-z));

    const float h0a = fmaf(Ae, init, Be);
    const float h0b = fmaf(A0, h0a, B0);
    g_h0[o0]      = h0a;
    g_h0[o0 + H_] = h0b;
}

// ---------------------------------------------------------------------------
// output replay: 128 threads per (b,chunk), each thread owns 2 channels.
// (reverted to the R10 measured-best form: __half2 loads, float2 stores)
// ---------------------------------------------------------------------------
__global__ __launch_bounds__(128) void k_out(float* __restrict__ out)
{
    const int bc = blockIdx.x;
    const int b  = bc / NCH;
    const int ch = bc % NCH;
    const int h2 = threadIdx.x * 2;
    size_t base = ((size_t)b * S_ + (size_t)ch * LCH) * H_ + h2;

    float hc0 = g_h0[(size_t)bc * H_ + h2];
    float hc1 = g_h0[(size_t)bc * H_ + h2 + 1];
#pragma unroll 4
    for (int t = 0; t < LCH; t++) {
        const size_t o = base + (size_t)t * H_;
        const __half2 a2 = *(const __half2*)&g_a[o];
        const __half2 c2 = *(const __half2*)&g_c[o];
        const float2 af = __half22float2(a2);
        const float2 cf = __half22float2(c2);
        hc0 = fmaf(af.x, hc0, cf.x);
        hc1 = fmaf(af.y, hc1, cf.y);
        float2 w; w.x = hc0; w.y = hc1;
        *(float2*)&out[o] = w;
    }
}

// ---------------------------------------------------------------------------
extern "C" void kernel_launch(void* const* d_in, const int* in_sizes, int n_in,
                              void* d_out, int out_size)
{
    const float* x  = nullptr;
    const float* hp = nullptr;
    const float* Wp = nullptr;
    for (int i = 0; i < n_in; i++) {
        if      (in_sizes[i] == M_ * D_)      x  = (const float*)d_in[i];
        else if (in_sizes[i] == B_ * H_)      hp = (const float*)d_in[i];
        else if (in_sizes[i] == 3 * H_ * D_)  Wp = (const float*)d_in[i];
    }
    float* out = (float*)d_out;

    cudaFuncSetAttribute(k_gemm_mma, cudaFuncAttributeMaxDynamicSharedMemorySize, SMEM_DYN);

    k_conv_w<<<(N3H * D_) / (256 * 4), 256>>>(Wp);

    dim3 gg(NTILES, M_ / MT);          // (4, 512)
    k_gemm_mma<<<gg, 256, SMEM_DYN>>>(x);

    k_chain<<<(B_ * H_ * 32) / 256, 256>>>(hp);
    k_out<<<B_ * NCH, 128>>>(out);
}